// round 4
// baseline (speedup 1.0000x reference)
#include <cuda_runtime.h>
#include <math.h>

#define BB 256
#define LL 1024
#define TT 64

// Scaled backward vectors (L, B, T). 64 MB static device scratch.
__device__ float g_sB[(size_t)LL * BB * TT];

// ---- packed f32x2 helpers (sm_103a) ----
#define FMA_F32X2(d, a, b, c) \
    asm("fma.rn.f32x2 %0, %1, %2, %3;" : "=l"(d) : "l"(a), "l"(b), "l"(c))
#define ADD_F32X2(d, a, b) \
    asm("add.rn.f32x2 %0, %1, %2;" : "=l"(d) : "l"(a), "l"(b))

__device__ __forceinline__ unsigned long long pack2(float lo, float hi) {
    unsigned long long r;
    asm("mov.b64 %0, {%1, %2};" : "=l"(r)
        : "r"(__float_as_uint(lo)), "r"(__float_as_uint(hi)));
    return r;
}
__device__ __forceinline__ float unpack_sum(unsigned long long v) {
    unsigned int lo, hi;
    asm("mov.b64 {%0, %1}, %2;" : "=r"(lo), "=r"(hi) : "l"(v));
    return __uint_as_float(lo) + __uint_as_float(hi);
}

// Packed matvec + vector sum in one pass over shared:
//   q = sum_j sh[j] * w[j]   (w2 = 32 packed weight pairs)
//   r = sum_j sh[j]
// Every thread reads the same shared values (broadcast, conflict-free).
__device__ __forceinline__ void matvec64r(const float* sh,
                                          const unsigned long long* w2,
                                          float& q, float& r) {
    const ulonglong2* sv = (const ulonglong2*)sh;
    unsigned long long qa = 0ull, qb = 0ull, qc = 0ull, qd = 0ull;
    unsigned long long ra = 0ull, rb = 0ull, rc = 0ull, rd = 0ull;
#pragma unroll
    for (int t = 0; t < 16; t += 2) {
        ulonglong2 v0 = sv[t];
        ulonglong2 v1 = sv[t + 1];
        FMA_F32X2(qa, v0.x, w2[2 * t + 0], qa);
        FMA_F32X2(qb, v0.y, w2[2 * t + 1], qb);
        FMA_F32X2(qc, v1.x, w2[2 * t + 2], qc);
        FMA_F32X2(qd, v1.y, w2[2 * t + 3], qd);
        ADD_F32X2(ra, ra, v0.x);
        ADD_F32X2(rb, rb, v0.y);
        ADD_F32X2(rc, rc, v1.x);
        ADD_F32X2(rd, rd, v1.y);
    }
    ADD_F32X2(qa, qa, qc);
    ADD_F32X2(qb, qb, qd);
    ADD_F32X2(qa, qa, qb);
    ADD_F32X2(ra, ra, rc);
    ADD_F32X2(rb, rb, rd);
    ADD_F32X2(ra, ra, rb);
    q = unpack_sum(qa);
    r = unpack_sum(ra);
}

// ---------------------------------------------------------------------------
// Fused scan, 2 batches per block (shared weights, shared syncs, 2 independent
// dependency chains per thread). Blocks [0, B/2): forward; [B/2, B): backward.
// Each direction carries its own Rabiner scaling; all scales cancel in the
// per-position normalization done by crf_combine.
// ---------------------------------------------------------------------------
__global__ __launch_bounds__(64) void crf_scan(
    const float* __restrict__ em,     // (B, L, T)
    const float* __restrict__ start,  // (T)
    const float* __restrict__ endt,   // (T)
    const float* __restrict__ trans,  // (T, T)
    const int*   __restrict__ mask,   // (B, L)
    float* __restrict__ sA)           // (L, B, T) = d_out
{
    const int k = threadIdx.x;        // this thread's tag

    __shared__ __align__(16) float sh[2][2][TT];  // [buf][batch][tag]
    __shared__ int shm[2][LL];

    if (blockIdx.x < BB / 2) {
        // ================= FORWARD (batches b0, b1) =================
        const int b0 = blockIdx.x * 2;
        const int b1 = b0 + 1;
        for (int i = k; i < LL; i += 64) {
            shm[0][i] = mask[b0 * LL + i];
            shm[1][i] = mask[b1 * LL + i];
        }

        // E column k, packed over j (shared by both batches)
        unsigned long long col2[TT / 2];
#pragma unroll
        for (int j2 = 0; j2 < TT / 2; ++j2)
            col2[j2] = pack2(expf(trans[(2 * j2) * TT + k]),
                             expf(trans[(2 * j2 + 1) * TT + k]));

        const float* e0 = em + (size_t)b0 * LL * TT + k;
        const float* e1 = em + (size_t)b1 * LL * TT + k;
        const float st = start[k];

        float s0 = expf(e0[0] + st);
        float s1 = expf(e1[0] + st);
        sA[(size_t)b0 * TT + k] = s0;
        sA[(size_t)b1 * TT + k] = s1;
        __syncthreads();

        float eb0[4], eb1[4];
#pragma unroll
        for (int u = 0; u < 4; ++u) {
            eb0[u] = expf(e0[(size_t)(1 + u) * TT]);
            eb1[u] = expf(e1[(size_t)(1 + u) * TT]);
        }

        for (int l0 = 1; l0 < LL; l0 += 4) {
            float en0[4], en1[4];
#pragma unroll
            for (int u = 0; u < 4; ++u) {
                int ln = l0 + 4 + u;
                en0[u] = (ln < LL) ? expf(e0[(size_t)ln * TT]) : 0.f;
                en1[u] = (ln < LL) ? expf(e1[(size_t)ln * TT]) : 0.f;
            }
#pragma unroll
            for (int u = 0; u < 4; ++u) {
                int l = l0 + u;
                if (l < LL) {
                    int buf = l & 1;
                    sh[buf][0][k] = s0;
                    sh[buf][1][k] = s1;
                    __syncthreads();
                    float q0, r0, q1, r1;
                    matvec64r(sh[buf][0], col2, q0, r0);
                    matvec64r(sh[buf][1], col2, q1, r1);
                    // r is uniform over k -> its precision cancels in combine
                    if (shm[0][l]) s0 = __fdividef(q0, r0) * eb0[u];
                    if (shm[1][l]) s1 = __fdividef(q1, r1) * eb1[u];
                    sA[(size_t)l * BB * TT + b0 * TT + k] = s0;
                    sA[(size_t)l * BB * TT + b1 * TT + k] = s1;
                }
            }
#pragma unroll
            for (int u = 0; u < 4; ++u) { eb0[u] = en0[u]; eb1[u] = en1[u]; }
        }
    } else {
        // ================= BACKWARD (batches b0, b1) =================
        const int b0 = (blockIdx.x - BB / 2) * 2;
        const int b1 = b0 + 1;
        const int j = k;
        for (int i = j; i < LL; i += 64) {
            shm[0][i] = mask[b0 * LL + i];
            shm[1][i] = mask[b1 * LL + i];
        }

        // E row j, packed over i (shared by both batches)
        unsigned long long row2[TT / 2];
#pragma unroll
        for (int i2 = 0; i2 < TT / 2; ++i2)
            row2[i2] = pack2(expf(trans[j * TT + 2 * i2]),
                             expf(trans[j * TT + 2 * i2 + 1]));

        const float* e0 = em + (size_t)b0 * LL * TT + j;
        const float* e1 = em + (size_t)b1 * LL * TT + j;

        float sb0 = expf(endt[j]);
        float sb1 = sb0;
        g_sB[(size_t)(LL - 1) * BB * TT + b0 * TT + j] = sb0;
        g_sB[(size_t)(LL - 1) * BB * TT + b1 * TT + j] = sb1;
        __syncthreads();

        float eb0[4], eb1[4];
#pragma unroll
        for (int u = 0; u < 4; ++u) {
            eb0[u] = expf(e0[(size_t)(LL - 1 - u) * TT]);
            eb1[u] = expf(e1[(size_t)(LL - 1 - u) * TT]);
        }

        for (int l0 = LL - 1; l0 >= 1; l0 -= 4) {
            float en0[4], en1[4];
#pragma unroll
            for (int u = 0; u < 4; ++u) {
                int ln = l0 - 4 - u;
                en0[u] = (ln >= 1) ? expf(e0[(size_t)ln * TT]) : 0.f;
                en1[u] = (ln >= 1) ? expf(e1[(size_t)ln * TT]) : 0.f;
            }
#pragma unroll
            for (int u = 0; u < 4; ++u) {
                int l = l0 - u;
                if (l >= 1) {
                    float t0 = sb0 * eb0[u];
                    float t1 = sb1 * eb1[u];
                    int buf = l & 1;
                    sh[buf][0][j] = t0;
                    sh[buf][1][j] = t1;
                    __syncthreads();
                    float q0, r0, q1, r1;
                    matvec64r(sh[buf][0], row2, q0, r0);
                    matvec64r(sh[buf][1], row2, q1, r1);
                    if (shm[0][l]) sb0 = __fdividef(q0, r0);
                    if (shm[1][l]) sb1 = __fdividef(q1, r1);
                    g_sB[(size_t)(l - 1) * BB * TT + b0 * TT + j] = sb0;
                    g_sB[(size_t)(l - 1) * BB * TT + b1 * TT + j] = sb1;
                }
            }
#pragma unroll
            for (int u = 0; u < 4; ++u) { eb0[u] = en0[u]; eb1[u] = en1[u]; }
        }
    }
}

// ---------------------------------------------------------------------------
// Combine: out[p, k] = sA[p,k]*sB[p,k] / sum_k(sA[p,k]*sB[p,k]).
// One position per 16 lanes, float4 per thread, shfl-only reduction.
// ---------------------------------------------------------------------------
__global__ __launch_bounds__(256) void crf_combine(
    float* __restrict__ outA)   // (L*B, T): in = sA, out = marginals
{
    const int lane = threadIdx.x & 31;
    const int warp = threadIdx.x >> 5;
    const int half = lane >> 4;          // which position within the warp
    const int sub  = lane & 15;          // float4 index within position
    const size_t p = (size_t)blockIdx.x * 16 + warp * 2 + half;

    const size_t f4 = p * (TT / 4) + sub;
    float4 a = ((const float4*)outA)[f4];
    float4 b = ((const float4*)g_sB)[f4];
    float4 v = make_float4(a.x * b.x, a.y * b.y, a.z * b.z, a.w * b.w);
    float s = (v.x + v.y) + (v.z + v.w);
    s += __shfl_xor_sync(0xffffffffu, s, 8);
    s += __shfl_xor_sync(0xffffffffu, s, 4);
    s += __shfl_xor_sync(0xffffffffu, s, 2);
    s += __shfl_xor_sync(0xffffffffu, s, 1);
    float inv = 1.f / s;
    ((float4*)outA)[f4] =
        make_float4(v.x * inv, v.y * inv, v.z * inv, v.w * inv);
}

extern "C" void kernel_launch(void* const* d_in, const int* in_sizes, int n_in,
                              void* d_out, int out_size) {
    const float* em    = (const float*)d_in[0];  // emissions (B,L,T)
    const float* start = (const float*)d_in[1];  // start_transitions (T)
    const float* endt  = (const float*)d_in[2];  // end_transitions (T)
    const float* trans = (const float*)d_in[3];  // transitions (T,T)
    const int*   mask  = (const int*)d_in[4];    // mask (B,L)
    float* out = (float*)d_out;                  // (L,B,T)

    crf_scan<<<BB, TT>>>(em, start, endt, trans, mask, out);
    crf_combine<<<(LL * BB) / 16, 256>>>(out);
}

// round 5
// speedup vs baseline: 2.2588x; 2.2588x over previous
#include <cuda_runtime.h>
#include <math.h>

#define BB 256
#define LL 1024
#define TT 64

// Scaled backward vectors (L, B, T). 64 MB static device scratch.
__device__ float g_sB[(size_t)LL * BB * TT];

// ---- packed f32x2 helpers (sm_103a) ----
#define FMA_F32X2(d, a, b, c) \
    asm("fma.rn.f32x2 %0, %1, %2, %3;" : "=l"(d) : "l"(a), "l"(b), "l"(c))
#define ADD_F32X2(d, a, b) \
    asm("add.rn.f32x2 %0, %1, %2;" : "=l"(d) : "l"(a), "l"(b))

__device__ __forceinline__ unsigned long long pack2(float lo, float hi) {
    unsigned long long r;
    asm("mov.b64 %0, {%1, %2};" : "=l"(r)
        : "r"(__float_as_uint(lo)), "r"(__float_as_uint(hi)));
    return r;
}
__device__ __forceinline__ float unpack_sum(unsigned long long v) {
    unsigned int lo, hi;
    asm("mov.b64 {%0, %1}, %2;" : "=r"(lo), "=r"(hi) : "l"(v));
    return __uint_as_float(lo) + __uint_as_float(hi);
}

// Packed matvec + vector sum in one pass over shared:
//   q = sum_j sh[j] * w[j]   (w2 = 32 packed weight pairs)
//   r = sum_j sh[j]
// All 64 threads broadcast-read the same shared addresses (conflict-free).
// The r-adds issue in the shadow of the FMA chain; removing the former
// shfl-tree reduction from the critical path.
__device__ __forceinline__ void matvec64r(const float* sh,
                                          const unsigned long long* w2,
                                          float& q, float& r) {
    const ulonglong2* sv = (const ulonglong2*)sh;
    unsigned long long qa = 0ull, qb = 0ull, qc = 0ull, qd = 0ull;
    unsigned long long ra = 0ull, rb = 0ull, rc = 0ull, rd = 0ull;
#pragma unroll
    for (int t = 0; t < 16; t += 2) {
        ulonglong2 v0 = sv[t];
        ulonglong2 v1 = sv[t + 1];
        FMA_F32X2(qa, v0.x, w2[2 * t + 0], qa);
        FMA_F32X2(qb, v0.y, w2[2 * t + 1], qb);
        FMA_F32X2(qc, v1.x, w2[2 * t + 2], qc);
        FMA_F32X2(qd, v1.y, w2[2 * t + 3], qd);
        ADD_F32X2(ra, ra, v0.x);
        ADD_F32X2(rb, rb, v0.y);
        ADD_F32X2(rc, rc, v1.x);
        ADD_F32X2(rd, rd, v1.y);
    }
    ADD_F32X2(qa, qa, qc);
    ADD_F32X2(qb, qb, qd);
    ADD_F32X2(qa, qa, qb);
    ADD_F32X2(ra, ra, rc);
    ADD_F32X2(rb, rb, rd);
    ADD_F32X2(ra, ra, rb);
    q = unpack_sum(qa);
    r = unpack_sum(ra);
}

// ---------------------------------------------------------------------------
// Fused scan, ONE batch per block (register footprint proven in R3).
// Blocks [0,B): forward recursion; blocks [B,2B): backward recursion.
// Each direction carries its own Rabiner scaling (r is uniform over tags, so
// every scale factor cancels in the per-position normalization in combine).
// ---------------------------------------------------------------------------
__global__ __launch_bounds__(64) void crf_scan(
    const float* __restrict__ em,     // (B, L, T)
    const float* __restrict__ start,  // (T)
    const float* __restrict__ endt,   // (T)
    const float* __restrict__ trans,  // (T, T)
    const int*   __restrict__ mask,   // (B, L)
    float* __restrict__ sA)           // (L, B, T) = d_out
{
    const int k = threadIdx.x;        // this thread's tag

    __shared__ __align__(16) float sh[2][TT];
    __shared__ int shm[LL];

    if (blockIdx.x < BB) {
        // ================= FORWARD =================
        const int b = blockIdx.x;
        for (int i = k; i < LL; i += 64) shm[i] = mask[b * LL + i];

        // E column k, packed over j
        unsigned long long col2[TT / 2];
#pragma unroll
        for (int j2 = 0; j2 < TT / 2; ++j2)
            col2[j2] = pack2(expf(trans[(2 * j2) * TT + k]),
                             expf(trans[(2 * j2 + 1) * TT + k]));

        const float* emb = em + (size_t)b * LL * TT + k;

        float s = expf(emb[0] + start[k]);
        sA[(size_t)b * TT + k] = s;  // l = 0
        __syncthreads();

        float ebuf[4];
#pragma unroll
        for (int u = 0; u < 4; ++u)
            ebuf[u] = expf(emb[(size_t)(1 + u) * TT]);

        for (int l0 = 1; l0 < LL; l0 += 4) {
            float enext[4];
#pragma unroll
            for (int u = 0; u < 4; ++u) {
                int ln = l0 + 4 + u;
                enext[u] = (ln < LL) ? expf(emb[(size_t)ln * TT]) : 0.f;
            }
#pragma unroll
            for (int u = 0; u < 4; ++u) {
                int l = l0 + u;
                if (l < LL) {
                    int buf = l & 1;
                    sh[buf][k] = s;
                    __syncthreads();
                    float q, r;
                    matvec64r(sh[buf], col2, q, r);
                    if (shm[l]) s = __fdividef(q, r) * ebuf[u];
                    sA[(size_t)l * BB * TT + b * TT + k] = s;
                }
            }
#pragma unroll
            for (int u = 0; u < 4; ++u) ebuf[u] = enext[u];
        }
    } else {
        // ================= BACKWARD =================
        const int b = blockIdx.x - BB;
        const int j = k;
        for (int i = j; i < LL; i += 64) shm[i] = mask[b * LL + i];

        // E row j, packed over i
        unsigned long long row2[TT / 2];
#pragma unroll
        for (int i2 = 0; i2 < TT / 2; ++i2)
            row2[i2] = pack2(expf(trans[j * TT + 2 * i2]),
                             expf(trans[j * TT + 2 * i2 + 1]));

        const float* emb = em + (size_t)b * LL * TT + j;

        float sb = expf(endt[j]);
        g_sB[(size_t)(LL - 1) * BB * TT + b * TT + j] = sb;  // l = L-1
        __syncthreads();

        float ebuf[4];
#pragma unroll
        for (int u = 0; u < 4; ++u)
            ebuf[u] = expf(emb[(size_t)(LL - 1 - u) * TT]);

        for (int l0 = LL - 1; l0 >= 1; l0 -= 4) {
            float enext[4];
#pragma unroll
            for (int u = 0; u < 4; ++u) {
                int ln = l0 - 4 - u;
                enext[u] = (ln >= 1) ? expf(emb[(size_t)ln * TT]) : 0.f;
            }
#pragma unroll
            for (int u = 0; u < 4; ++u) {
                int l = l0 - u;
                if (l >= 1) {
                    float t = sb * ebuf[u];
                    int buf = l & 1;
                    sh[buf][j] = t;
                    __syncthreads();
                    float q, r;
                    matvec64r(sh[buf], row2, q, r);
                    if (shm[l]) sb = __fdividef(q, r);
                    g_sB[(size_t)(l - 1) * BB * TT + b * TT + j] = sb;
                }
            }
#pragma unroll
            for (int u = 0; u < 4; ++u) ebuf[u] = enext[u];
        }
    }
}

// ---------------------------------------------------------------------------
// Combine: out[p, k] = sA[p,k]*sB[p,k] / sum_k(sA[p,k]*sB[p,k]).
// One position per 16 lanes, float4 per thread, shfl-only reduction.
// ---------------------------------------------------------------------------
__global__ __launch_bounds__(256) void crf_combine(
    float* __restrict__ outA)   // (L*B, T): in = sA, out = marginals
{
    const int lane = threadIdx.x & 31;
    const int warp = threadIdx.x >> 5;
    const int half = lane >> 4;          // which position within the warp
    const int sub  = lane & 15;          // float4 index within position
    const size_t p = (size_t)blockIdx.x * 16 + warp * 2 + half;

    const size_t f4 = p * (TT / 4) + sub;
    float4 a = ((const float4*)outA)[f4];
    float4 b = ((const float4*)g_sB)[f4];
    float4 v = make_float4(a.x * b.x, a.y * b.y, a.z * b.z, a.w * b.w);
    float s = (v.x + v.y) + (v.z + v.w);
    s += __shfl_xor_sync(0xffffffffu, s, 8);
    s += __shfl_xor_sync(0xffffffffu, s, 4);
    s += __shfl_xor_sync(0xffffffffu, s, 2);
    s += __shfl_xor_sync(0xffffffffu, s, 1);
    float inv = 1.f / s;
    ((float4*)outA)[f4] =
        make_float4(v.x * inv, v.y * inv, v.z * inv, v.w * inv);
}

extern "C" void kernel_launch(void* const* d_in, const int* in_sizes, int n_in,
                              void* d_out, int out_size) {
    const float* em    = (const float*)d_in[0];  // emissions (B,L,T)
    const float* start = (const float*)d_in[1];  // start_transitions (T)
    const float* endt  = (const float*)d_in[2];  // end_transitions (T)
    const float* trans = (const float*)d_in[3];  // transitions (T,T)
    const int*   mask  = (const int*)d_in[4];    // mask (B,L)
    float* out = (float*)d_out;                  // (L,B,T)

    crf_scan<<<2 * BB, TT>>>(em, start, endt, trans, mask, out);
    crf_combine<<<(LL * BB) / 16, 256>>>(out);
}

// round 6
// speedup vs baseline: 2.3085x; 1.0220x over previous
#include <cuda_runtime.h>
#include <math.h>

#define BB 256
#define LL 1024
#define TT 64

// Scaled backward vectors (L, B, T). 64 MB static device scratch.
__device__ float g_sB[(size_t)LL * BB * TT];

// ---- packed f32x2 helpers (sm_103a) ----
#define FMA_F32X2(d, a, b, c) \
    asm("fma.rn.f32x2 %0, %1, %2, %3;" : "=l"(d) : "l"(a), "l"(b), "l"(c))
#define ADD_F32X2(d, a, b) \
    asm("add.rn.f32x2 %0, %1, %2;" : "=l"(d) : "l"(a), "l"(b))

__device__ __forceinline__ unsigned long long pack2(float lo, float hi) {
    unsigned long long r;
    asm("mov.b64 %0, {%1, %2};" : "=l"(r)
        : "r"(__float_as_uint(lo)), "r"(__float_as_uint(hi)));
    return r;
}
__device__ __forceinline__ float unpack_sum(unsigned long long v) {
    unsigned int lo, hi;
    asm("mov.b64 {%0, %1}, %2;" : "=r"(lo), "=r"(hi) : "l"(v));
    return __uint_as_float(lo) + __uint_as_float(hi);
}

// q = sum_j sh[j] * w[j]  (matvec only)
__device__ __forceinline__ void matvec64q(const float* sh,
                                          const unsigned long long* w2,
                                          float& q) {
    const ulonglong2* sv = (const ulonglong2*)sh;
    unsigned long long qa = 0ull, qb = 0ull, qc = 0ull, qd = 0ull;
#pragma unroll
    for (int t = 0; t < 16; t += 2) {
        ulonglong2 v0 = sv[t];
        ulonglong2 v1 = sv[t + 1];
        FMA_F32X2(qa, v0.x, w2[2 * t + 0], qa);
        FMA_F32X2(qb, v0.y, w2[2 * t + 1], qb);
        FMA_F32X2(qc, v1.x, w2[2 * t + 2], qc);
        FMA_F32X2(qd, v1.y, w2[2 * t + 3], qd);
    }
    ADD_F32X2(qa, qa, qc);
    ADD_F32X2(qb, qb, qd);
    ADD_F32X2(qa, qa, qb);
    q = unpack_sum(qa);
}

// q = sum_j sh[j]*w[j], r = sum_j sh[j]  (normalization steps only)
__device__ __forceinline__ void matvec64qr(const float* sh,
                                           const unsigned long long* w2,
                                           float& q, float& r) {
    const ulonglong2* sv = (const ulonglong2*)sh;
    unsigned long long qa = 0ull, qb = 0ull, qc = 0ull, qd = 0ull;
    unsigned long long ra = 0ull, rb = 0ull, rc = 0ull, rd = 0ull;
#pragma unroll
    for (int t = 0; t < 16; t += 2) {
        ulonglong2 v0 = sv[t];
        ulonglong2 v1 = sv[t + 1];
        FMA_F32X2(qa, v0.x, w2[2 * t + 0], qa);
        FMA_F32X2(qb, v0.y, w2[2 * t + 1], qb);
        FMA_F32X2(qc, v1.x, w2[2 * t + 2], qc);
        FMA_F32X2(qd, v1.y, w2[2 * t + 3], qd);
        ADD_F32X2(ra, ra, v0.x);
        ADD_F32X2(rb, rb, v0.y);
        ADD_F32X2(rc, rc, v1.x);
        ADD_F32X2(rd, rd, v1.y);
    }
    ADD_F32X2(qa, qa, qc);
    ADD_F32X2(qb, qb, qd);
    ADD_F32X2(qa, qa, qb);
    ADD_F32X2(ra, ra, rc);
    ADD_F32X2(rb, rb, rd);
    ADD_F32X2(ra, ra, rb);
    q = unpack_sum(qa);
    r = unpack_sum(ra);
}

// group-scoped barrier: 64 threads, named barrier (g+1)
#define GBAR(barid) asm volatile("bar.sync %0, 64;" :: "r"(barid) : "memory")

// ---------------------------------------------------------------------------
// Fused scan. 128-thread blocks = 4 warps (one per SMSP: wid%4 mapping).
// Each block hosts TWO independent 64-thread groups; group g runs task
// blockIdx*2+g. Tasks [0,B): forward; [B,2B): backward. Groups sync with
// named barriers so they never couple. Scaling is normalized only every 2nd
// step (uniform over tags -> cancels exactly in the combine normalization).
// ---------------------------------------------------------------------------
__global__ __launch_bounds__(128) void crf_scan(
    const float* __restrict__ em,     // (B, L, T)
    const float* __restrict__ start,  // (T)
    const float* __restrict__ endt,   // (T)
    const float* __restrict__ trans,  // (T, T)
    const int*   __restrict__ mask,   // (B, L)
    float* __restrict__ sA)           // (L, B, T) = d_out
{
    const int tid = threadIdx.x;
    const int g   = tid >> 6;         // group 0/1 within the block
    const int k   = tid & 63;         // this thread's tag
    const int task = blockIdx.x * 2 + g;
    const int barid = g + 1;

    __shared__ __align__(16) float sh[2][2][TT];   // [group][buf][tag]
    __shared__ int shm[2][LL];

    if (task < BB) {
        // ================= FORWARD =================
        const int b = task;
        for (int i = k; i < LL; i += 64) shm[g][i] = mask[b * LL + i];

        unsigned long long col2[TT / 2];
#pragma unroll
        for (int j2 = 0; j2 < TT / 2; ++j2)
            col2[j2] = pack2(expf(trans[(2 * j2) * TT + k]),
                             expf(trans[(2 * j2 + 1) * TT + k]));

        const float* emb = em + (size_t)b * LL * TT + k;

        float s = expf(emb[0] + start[k]);
        sA[(size_t)b * TT + k] = s;  // l = 0

        float ebuf[4];
#pragma unroll
        for (int u = 0; u < 4; ++u)
            ebuf[u] = expf(emb[(size_t)(1 + u) * TT]);

        for (int l0 = 1; l0 < LL; l0 += 4) {
            float enext[4];
#pragma unroll
            for (int u = 0; u < 4; ++u) {
                int ln = l0 + 4 + u;
                enext[u] = (ln < LL) ? expf(emb[(size_t)ln * TT]) : 0.f;
            }
#pragma unroll
            for (int u = 0; u < 4; ++u) {
                int l = l0 + u;
                if (l < LL) {
                    int buf = l & 1;
                    sh[g][buf][k] = s;
                    GBAR(barid);
                    if (u & 1) {  // normalize every 2nd step
                        float q, r;
                        matvec64qr(sh[g][buf], col2, q, r);
                        if (shm[g][l]) s = __fdividef(q, r) * ebuf[u];
                    } else {      // unscaled step (growth bounded, cancels)
                        float q;
                        matvec64q(sh[g][buf], col2, q);
                        if (shm[g][l]) s = q * ebuf[u];
                    }
                    sA[(size_t)l * BB * TT + b * TT + k] = s;
                }
            }
#pragma unroll
            for (int u = 0; u < 4; ++u) ebuf[u] = enext[u];
        }
    } else {
        // ================= BACKWARD =================
        const int b = task - BB;
        const int j = k;
        for (int i = j; i < LL; i += 64) shm[g][i] = mask[b * LL + i];

        unsigned long long row2[TT / 2];
#pragma unroll
        for (int i2 = 0; i2 < TT / 2; ++i2)
            row2[i2] = pack2(expf(trans[j * TT + 2 * i2]),
                             expf(trans[j * TT + 2 * i2 + 1]));

        const float* emb = em + (size_t)b * LL * TT + j;

        float sb = expf(endt[j]);
        g_sB[(size_t)(LL - 1) * BB * TT + b * TT + j] = sb;  // l = L-1

        float ebuf[4];
#pragma unroll
        for (int u = 0; u < 4; ++u)
            ebuf[u] = expf(emb[(size_t)(LL - 1 - u) * TT]);

        for (int l0 = LL - 1; l0 >= 1; l0 -= 4) {
            float enext[4];
#pragma unroll
            for (int u = 0; u < 4; ++u) {
                int ln = l0 - 4 - u;
                enext[u] = (ln >= 1) ? expf(emb[(size_t)ln * TT]) : 0.f;
            }
#pragma unroll
            for (int u = 0; u < 4; ++u) {
                int l = l0 - u;
                if (l >= 1) {
                    float t = sb * ebuf[u];
                    int buf = l & 1;
                    sh[g][buf][j] = t;
                    GBAR(barid);
                    if (u & 1) {  // normalize every 2nd step
                        float q, r;
                        matvec64qr(sh[g][buf], row2, q, r);
                        if (shm[g][l]) sb = __fdividef(q, r);
                    } else {
                        float q;
                        matvec64q(sh[g][buf], row2, q);
                        if (shm[g][l]) sb = q;
                    }
                    g_sB[(size_t)(l - 1) * BB * TT + b * TT + j] = sb;
                }
            }
#pragma unroll
            for (int u = 0; u < 4; ++u) ebuf[u] = enext[u];
        }
    }
}

// ---------------------------------------------------------------------------
// Combine: out[p, k] = sA[p,k]*sB[p,k] / sum_k(sA[p,k]*sB[p,k]).
// One position per 16 lanes, float4 per thread, shfl-only reduction.
// ---------------------------------------------------------------------------
__global__ __launch_bounds__(256) void crf_combine(
    float* __restrict__ outA)   // (L*B, T): in = sA, out = marginals
{
    const int lane = threadIdx.x & 31;
    const int warp = threadIdx.x >> 5;
    const int half = lane >> 4;          // which position within the warp
    const int sub  = lane & 15;          // float4 index within position
    const size_t p = (size_t)blockIdx.x * 16 + warp * 2 + half;

    const size_t f4 = p * (TT / 4) + sub;
    float4 a = ((const float4*)outA)[f4];
    float4 b = ((const float4*)g_sB)[f4];
    float4 v = make_float4(a.x * b.x, a.y * b.y, a.z * b.z, a.w * b.w);
    float s = (v.x + v.y) + (v.z + v.w);
    s += __shfl_xor_sync(0xffffffffu, s, 8);
    s += __shfl_xor_sync(0xffffffffu, s, 4);
    s += __shfl_xor_sync(0xffffffffu, s, 2);
    s += __shfl_xor_sync(0xffffffffu, s, 1);
    float inv = 1.f / s;
    ((float4*)outA)[f4] =
        make_float4(v.x * inv, v.y * inv, v.z * inv, v.w * inv);
}

extern "C" void kernel_launch(void* const* d_in, const int* in_sizes, int n_in,
                              void* d_out, int out_size) {
    const float* em    = (const float*)d_in[0];  // emissions (B,L,T)
    const float* start = (const float*)d_in[1];  // start_transitions (T)
    const float* endt  = (const float*)d_in[2];  // end_transitions (T)
    const float* trans = (const float*)d_in[3];  // transitions (T,T)
    const int*   mask  = (const int*)d_in[4];    // mask (B,L)
    float* out = (float*)d_out;                  // (L,B,T)

    crf_scan<<<BB, 128>>>(em, start, endt, trans, mask, out);
    crf_combine<<<(LL * BB) / 16, 256>>>(out);
}

// round 7
// speedup vs baseline: 3.0108x; 1.3042x over previous
#include <cuda_runtime.h>
#include <math.h>

#define BB 256
#define LL 1024
#define TT 64

// Scaled backward vectors (L, B, T). 64 MB static device scratch.
__device__ float g_sB[(size_t)LL * BB * TT];

// ---- packed f32x2 helpers (sm_103a) ----
#define FMA_F32X2(d, a, b, c) \
    asm("fma.rn.f32x2 %0, %1, %2, %3;" : "=l"(d) : "l"(a), "l"(b), "l"(c))
#define ADD_F32X2(d, a, b) \
    asm("add.rn.f32x2 %0, %1, %2;" : "=l"(d) : "l"(a), "l"(b))

__device__ __forceinline__ unsigned long long pack2(float lo, float hi) {
    unsigned long long r;
    asm("mov.b64 %0, {%1, %2};" : "=l"(r)
        : "r"(__float_as_uint(lo)), "r"(__float_as_uint(hi)));
    return r;
}
__device__ __forceinline__ float unpack_sum(unsigned long long v) {
    unsigned int lo, hi;
    asm("mov.b64 {%0, %1}, %2;" : "=r"(lo), "=r"(hi) : "l"(v));
    return __uint_as_float(lo) + __uint_as_float(hi);
}

// q = sum_j sh[j] * w[j]  (matvec only)
__device__ __forceinline__ void matvec64q(const float* sh,
                                          const unsigned long long* w2,
                                          float& q) {
    const ulonglong2* sv = (const ulonglong2*)sh;
    unsigned long long qa = 0ull, qb = 0ull, qc = 0ull, qd = 0ull;
#pragma unroll
    for (int t = 0; t < 16; t += 2) {
        ulonglong2 v0 = sv[t];
        ulonglong2 v1 = sv[t + 1];
        FMA_F32X2(qa, v0.x, w2[2 * t + 0], qa);
        FMA_F32X2(qb, v0.y, w2[2 * t + 1], qb);
        FMA_F32X2(qc, v1.x, w2[2 * t + 2], qc);
        FMA_F32X2(qd, v1.y, w2[2 * t + 3], qd);
    }
    ADD_F32X2(qa, qa, qc);
    ADD_F32X2(qb, qb, qd);
    ADD_F32X2(qa, qa, qb);
    q = unpack_sum(qa);
}

// q = sum_j sh[j]*w[j], r = sum_j sh[j]  (normalization steps only)
__device__ __forceinline__ void matvec64qr(const float* sh,
                                           const unsigned long long* w2,
                                           float& q, float& r) {
    const ulonglong2* sv = (const ulonglong2*)sh;
    unsigned long long qa = 0ull, qb = 0ull, qc = 0ull, qd = 0ull;
    unsigned long long ra = 0ull, rb = 0ull, rc = 0ull, rd = 0ull;
#pragma unroll
    for (int t = 0; t < 16; t += 2) {
        ulonglong2 v0 = sv[t];
        ulonglong2 v1 = sv[t + 1];
        FMA_F32X2(qa, v0.x, w2[2 * t + 0], qa);
        FMA_F32X2(qb, v0.y, w2[2 * t + 1], qb);
        FMA_F32X2(qc, v1.x, w2[2 * t + 2], qc);
        FMA_F32X2(qd, v1.y, w2[2 * t + 3], qd);
        ADD_F32X2(ra, ra, v0.x);
        ADD_F32X2(rb, rb, v0.y);
        ADD_F32X2(rc, rc, v1.x);
        ADD_F32X2(rd, rd, v1.y);
    }
    ADD_F32X2(qa, qa, qc);
    ADD_F32X2(qb, qb, qd);
    ADD_F32X2(qa, qa, qb);
    ADD_F32X2(ra, ra, rc);
    ADD_F32X2(rb, rb, rd);
    ADD_F32X2(ra, ra, rb);
    q = unpack_sum(qa);
    r = unpack_sum(ra);
}

// group-scoped barrier: 64 threads, named barrier (g+1)
#define GBAR(barid) asm volatile("bar.sync %0, 64;" :: "r"(barid) : "memory")

// ---------------------------------------------------------------------------
// Fused scan. 128-thread blocks; two independent 64-thread groups per block,
// each running one (batch, direction) task, synced by named barriers.
// Emission pipeline: raw LDG issued 2 groups (8 steps, ~1200cy) ahead;
// exp-conversion done 1 group ahead from registers. This keeps DRAM latency
// off the per-step critical chain (the R6 bottleneck).
// Rabiner-style scaling, normalized every 2nd step; scale factors are uniform
// over tags and cancel exactly in crf_combine's per-position normalization.
// ---------------------------------------------------------------------------
__global__ __launch_bounds__(128) void crf_scan(
    const float* __restrict__ em,     // (B, L, T)
    const float* __restrict__ start,  // (T)
    const float* __restrict__ endt,   // (T)
    const float* __restrict__ trans,  // (T, T)
    const int*   __restrict__ mask,   // (B, L)
    float* __restrict__ sA)           // (L, B, T) = d_out
{
    const int tid = threadIdx.x;
    const int g   = tid >> 6;         // group 0/1 within the block
    const int k   = tid & 63;         // this thread's tag
    const int task = blockIdx.x * 2 + g;
    const int barid = g + 1;

    __shared__ __align__(16) float sh[2][2][TT];   // [group][buf][tag]
    __shared__ int shm[2][LL];

    if (task < BB) {
        // ================= FORWARD =================
        const int b = task;
        for (int i = k; i < LL; i += 64) shm[g][i] = mask[b * LL + i];

        unsigned long long col2[TT / 2];
#pragma unroll
        for (int j2 = 0; j2 < TT / 2; ++j2)
            col2[j2] = pack2(expf(trans[(2 * j2) * TT + k]),
                             expf(trans[(2 * j2 + 1) * TT + k]));

        const float* emb = em + (size_t)b * LL * TT + k;

        float s = __expf(emb[0] + start[k]);
        sA[(size_t)b * TT + k] = s;  // l = 0

        // ---- emission pipeline prologue ----
        // eb: exp'd ems for current group; rb: raw ems for next group.
        float eb[4], rb[4];
#pragma unroll
        for (int u = 0; u < 4; ++u) {
            int ln = 1 + u;
            eb[u] = __expf(emb[(size_t)ln * TT]);   // group 0 (one-time stall)
        }
#pragma unroll
        for (int u = 0; u < 4; ++u) {
            int ln = 5 + u;
            rb[u] = (ln < LL) ? emb[(size_t)ln * TT] : 0.f;  // raw, group 1
        }

        for (int l0 = 1; l0 < LL; l0 += 4) {
            // issue raw loads for group g+2 (consumed as exp 4 steps later)
            float rnext[4];
#pragma unroll
            for (int u = 0; u < 4; ++u) {
                int ln = l0 + 8 + u;
                rnext[u] = (ln < LL) ? emb[(size_t)ln * TT] : 0.f;
            }
            // convert raw (group g+1, loaded ~4 steps ago) to exp
            float enext[4];
#pragma unroll
            for (int u = 0; u < 4; ++u) enext[u] = __expf(rb[u]);

#pragma unroll
            for (int u = 0; u < 4; ++u) {
                int l = l0 + u;
                if (l < LL) {
                    int buf = l & 1;
                    sh[g][buf][k] = s;
                    GBAR(barid);
                    if (u & 1) {  // normalize every 2nd step
                        float q, r;
                        matvec64qr(sh[g][buf], col2, q, r);
                        if (shm[g][l]) s = __fdividef(q, r) * eb[u];
                    } else {      // unscaled step (growth bounded, cancels)
                        float q;
                        matvec64q(sh[g][buf], col2, q);
                        if (shm[g][l]) s = q * eb[u];
                    }
                    sA[(size_t)l * BB * TT + b * TT + k] = s;
                }
            }
#pragma unroll
            for (int u = 0; u < 4; ++u) { eb[u] = enext[u]; rb[u] = rnext[u]; }
        }
    } else {
        // ================= BACKWARD =================
        const int b = task - BB;
        const int j = k;
        for (int i = j; i < LL; i += 64) shm[g][i] = mask[b * LL + i];

        unsigned long long row2[TT / 2];
#pragma unroll
        for (int i2 = 0; i2 < TT / 2; ++i2)
            row2[i2] = pack2(expf(trans[j * TT + 2 * i2]),
                             expf(trans[j * TT + 2 * i2 + 1]));

        const float* emb = em + (size_t)b * LL * TT + j;

        float sb = __expf(endt[j]);
        g_sB[(size_t)(LL - 1) * BB * TT + b * TT + j] = sb;  // l = L-1

        // ---- emission pipeline prologue (descending l) ----
        float eb[4], rb[4];
#pragma unroll
        for (int u = 0; u < 4; ++u) {
            int ln = (LL - 1) - u;
            eb[u] = __expf(emb[(size_t)ln * TT]);
        }
#pragma unroll
        for (int u = 0; u < 4; ++u) {
            int ln = (LL - 5) - u;
            rb[u] = (ln >= 1) ? emb[(size_t)ln * TT] : 0.f;
        }

        for (int l0 = LL - 1; l0 >= 1; l0 -= 4) {
            float rnext[4];
#pragma unroll
            for (int u = 0; u < 4; ++u) {
                int ln = l0 - 8 - u;
                rnext[u] = (ln >= 1) ? emb[(size_t)ln * TT] : 0.f;
            }
            float enext[4];
#pragma unroll
            for (int u = 0; u < 4; ++u) enext[u] = __expf(rb[u]);

#pragma unroll
            for (int u = 0; u < 4; ++u) {
                int l = l0 - u;
                if (l >= 1) {
                    float t = sb * eb[u];
                    int buf = l & 1;
                    sh[g][buf][j] = t;
                    GBAR(barid);
                    if (u & 1) {  // normalize every 2nd step
                        float q, r;
                        matvec64qr(sh[g][buf], row2, q, r);
                        if (shm[g][l]) sb = __fdividef(q, r);
                    } else {
                        float q;
                        matvec64q(sh[g][buf], row2, q);
                        if (shm[g][l]) sb = q;
                    }
                    g_sB[(size_t)(l - 1) * BB * TT + b * TT + j] = sb;
                }
            }
#pragma unroll
            for (int u = 0; u < 4; ++u) { eb[u] = enext[u]; rb[u] = rnext[u]; }
        }
    }
}

// ---------------------------------------------------------------------------
// Combine: out[p, k] = sA[p,k]*sB[p,k] / sum_k(sA[p,k]*sB[p,k]).
// One position per 16 lanes, float4 per thread, shfl-only reduction.
// ---------------------------------------------------------------------------
__global__ __launch_bounds__(256) void crf_combine(
    float* __restrict__ outA)   // (L*B, T): in = sA, out = marginals
{
    const int lane = threadIdx.x & 31;
    const int warp = threadIdx.x >> 5;
    const int half = lane >> 4;          // which position within the warp
    const int sub  = lane & 15;          // float4 index within position
    const size_t p = (size_t)blockIdx.x * 16 + warp * 2 + half;

    const size_t f4 = p * (TT / 4) + sub;
    float4 a = ((const float4*)outA)[f4];
    float4 b = ((const float4*)g_sB)[f4];
    float4 v = make_float4(a.x * b.x, a.y * b.y, a.z * b.z, a.w * b.w);
    float s = (v.x + v.y) + (v.z + v.w);
    s += __shfl_xor_sync(0xffffffffu, s, 8);
    s += __shfl_xor_sync(0xffffffffu, s, 4);
    s += __shfl_xor_sync(0xffffffffu, s, 2);
    s += __shfl_xor_sync(0xffffffffu, s, 1);
    float inv = 1.f / s;
    ((float4*)outA)[f4] =
        make_float4(v.x * inv, v.y * inv, v.z * inv, v.w * inv);
}

extern "C" void kernel_launch(void* const* d_in, const int* in_sizes, int n_in,
                              void* d_out, int out_size) {
    const float* em    = (const float*)d_in[0];  // emissions (B,L,T)
    const float* start = (const float*)d_in[1];  // start_transitions (T)
    const float* endt  = (const float*)d_in[2];  // end_transitions (T)
    const float* trans = (const float*)d_in[3];  // transitions (T,T)
    const int*   mask  = (const int*)d_in[4];    // mask (B,L)
    float* out = (float*)d_out;                  // (L,B,T)

    crf_scan<<<BB, 128>>>(em, start, endt, trans, mask, out);
    crf_combine<<<(LL * BB) / 16, 256>>>(out);
}

// round 8
// speedup vs baseline: 3.4156x; 1.1345x over previous
#include <cuda_runtime.h>
#include <math.h>

#define BB 256
#define LL 1024
#define TT 64

// Scaled backward vectors (L, B, T). 64 MB static device scratch.
__device__ float g_sB[(size_t)LL * BB * TT];

// ---- packed f32x2 helpers (sm_103a) ----
#define FMA_F32X2(d, a, b, c) \
    asm("fma.rn.f32x2 %0, %1, %2, %3;" : "=l"(d) : "l"(a), "l"(b), "l"(c))
#define ADD_F32X2(d, a, b) \
    asm("add.rn.f32x2 %0, %1, %2;" : "=l"(d) : "l"(a), "l"(b))

__device__ __forceinline__ unsigned long long pack2(float lo, float hi) {
    unsigned long long r;
    asm("mov.b64 %0, {%1, %2};" : "=l"(r)
        : "r"(__float_as_uint(lo)), "r"(__float_as_uint(hi)));
    return r;
}
__device__ __forceinline__ float unpack_sum(unsigned long long v) {
    unsigned int lo, hi;
    asm("mov.b64 {%0, %1}, %2;" : "=r"(lo), "=r"(hi) : "l"(v));
    return __uint_as_float(lo) + __uint_as_float(hi);
}

// Dual-tag matvec: qA = sum_j sh[j]*wA[j], qB = sum_j sh[j]*wB[j].
// The 16 broadcast LDS.128 are shared by both accumulations.
__device__ __forceinline__ void matvec2(const float* shbuf,
                                        const unsigned long long* wA,
                                        const unsigned long long* wB,
                                        float& qA, float& qB) {
    const ulonglong2* sv = (const ulonglong2*)shbuf;
    unsigned long long a0 = 0, a1 = 0, a2 = 0, a3 = 0;
    unsigned long long b0 = 0, b1 = 0, b2 = 0, b3 = 0;
#pragma unroll
    for (int t = 0; t < 16; t += 2) {
        ulonglong2 v0 = sv[t];
        ulonglong2 v1 = sv[t + 1];
        FMA_F32X2(a0, v0.x, wA[2 * t + 0], a0);
        FMA_F32X2(a1, v0.y, wA[2 * t + 1], a1);
        FMA_F32X2(a2, v1.x, wA[2 * t + 2], a2);
        FMA_F32X2(a3, v1.y, wA[2 * t + 3], a3);
        FMA_F32X2(b0, v0.x, wB[2 * t + 0], b0);
        FMA_F32X2(b1, v0.y, wB[2 * t + 1], b1);
        FMA_F32X2(b2, v1.x, wB[2 * t + 2], b2);
        FMA_F32X2(b3, v1.y, wB[2 * t + 3], b3);
    }
    ADD_F32X2(a0, a0, a2);
    ADD_F32X2(a1, a1, a3);
    ADD_F32X2(a0, a0, a1);
    ADD_F32X2(b0, b0, b2);
    ADD_F32X2(b1, b1, b3);
    ADD_F32X2(b0, b0, b1);
    qA = unpack_sum(a0);
    qB = unpack_sum(b0);
}

// Same plus vector sum r = sum_j sh[j] (normalization steps only).
__device__ __forceinline__ void matvec2r(const float* shbuf,
                                         const unsigned long long* wA,
                                         const unsigned long long* wB,
                                         float& qA, float& qB, float& r) {
    const ulonglong2* sv = (const ulonglong2*)shbuf;
    unsigned long long a0 = 0, a1 = 0, a2 = 0, a3 = 0;
    unsigned long long b0 = 0, b1 = 0, b2 = 0, b3 = 0;
    unsigned long long r0 = 0, r1 = 0, r2 = 0, r3 = 0;
#pragma unroll
    for (int t = 0; t < 16; t += 2) {
        ulonglong2 v0 = sv[t];
        ulonglong2 v1 = sv[t + 1];
        FMA_F32X2(a0, v0.x, wA[2 * t + 0], a0);
        FMA_F32X2(a1, v0.y, wA[2 * t + 1], a1);
        FMA_F32X2(a2, v1.x, wA[2 * t + 2], a2);
        FMA_F32X2(a3, v1.y, wA[2 * t + 3], a3);
        FMA_F32X2(b0, v0.x, wB[2 * t + 0], b0);
        FMA_F32X2(b1, v0.y, wB[2 * t + 1], b1);
        FMA_F32X2(b2, v1.x, wB[2 * t + 2], b2);
        FMA_F32X2(b3, v1.y, wB[2 * t + 3], b3);
        ADD_F32X2(r0, r0, v0.x);
        ADD_F32X2(r1, r1, v0.y);
        ADD_F32X2(r2, r2, v1.x);
        ADD_F32X2(r3, r3, v1.y);
    }
    ADD_F32X2(a0, a0, a2);
    ADD_F32X2(a1, a1, a3);
    ADD_F32X2(a0, a0, a1);
    ADD_F32X2(b0, b0, b2);
    ADD_F32X2(b1, b1, b3);
    ADD_F32X2(b0, b0, b1);
    ADD_F32X2(r0, r0, r2);
    ADD_F32X2(r1, r1, r3);
    ADD_F32X2(r0, r0, r1);
    qA = unpack_sum(a0);
    qB = unpack_sum(b0);
    r = unpack_sum(r0);
}

// ---------------------------------------------------------------------------
// Fused scan: ONE WARP PER TASK. Thread `lane` owns tags (2*lane, 2*lane+1).
// Per-step exchange is warp-internal (STS.64 + __syncwarp + broadcast LDS),
// no block barriers. 128-thread blocks = 4 independent warp-tasks, one per
// SMSP. Tasks [0,B): forward; [B,2B): backward. Rabiner-style scaling,
// normalized every 2nd step; scale is uniform over tags and cancels exactly
// in crf_combine's per-position normalization.
// ---------------------------------------------------------------------------
__global__ __launch_bounds__(128) void crf_scan(
    const float* __restrict__ em,     // (B, L, T)
    const float* __restrict__ start,  // (T)
    const float* __restrict__ endt,   // (T)
    const float* __restrict__ trans,  // (T, T)
    const int*   __restrict__ mask,   // (B, L)
    float* __restrict__ sA)           // (L, B, T) = d_out
{
    const int lane = threadIdx.x & 31;
    const int w    = threadIdx.x >> 5;
    const int task = blockIdx.x * 4 + w;
    const int tAi  = 2 * lane;          // first owned tag
    const int tBi  = tAi + 1;           // second owned tag

    __shared__ __align__(16) float sh[4][2][TT];   // [warp][buf][tag]

    if (task < BB) {
        // ================= FORWARD =================
        const int b = task;

        // E columns tA, tB packed over j
        unsigned long long colA[TT / 2], colB[TT / 2];
#pragma unroll
        for (int j2 = 0; j2 < TT / 2; ++j2) {
            colA[j2] = pack2(expf(trans[(2 * j2) * TT + tAi]),
                             expf(trans[(2 * j2 + 1) * TT + tAi]));
            colB[j2] = pack2(expf(trans[(2 * j2) * TT + tBi]),
                             expf(trans[(2 * j2 + 1) * TT + tBi]));
        }

        const float2* emb = (const float2*)(em + (size_t)b * LL * TT) + lane;
        const int* mk = mask + b * LL;

        float2 e00 = emb[0];
        float sa = __expf(e00.x + start[tAi]);
        float sb = __expf(e00.y + start[tBi]);
        ((float2*)(sA + (size_t)b * TT))[lane] = make_float2(sa, sb);

        // pipeline: exp'd ems + mask for current group; raw for next group
        float ebA[4], ebB[4];
        float2 rb[4];
        int mcur[4], mraw[4];
#pragma unroll
        for (int u = 0; u < 4; ++u) {
            float2 v = emb[(size_t)(1 + u) * (TT / 2)];
            ebA[u] = __expf(v.x);
            ebB[u] = __expf(v.y);
            mcur[u] = mk[1 + u];
        }
#pragma unroll
        for (int u = 0; u < 4; ++u) {
            int ln = 5 + u;
            rb[u]   = (ln < LL) ? emb[(size_t)ln * (TT / 2)] : make_float2(0.f, 0.f);
            mraw[u] = (ln < LL) ? mk[ln] : 0;
        }

        for (int l0 = 1; l0 < LL; l0 += 4) {
            float2 rnext[4];
            int mnext[4];
#pragma unroll
            for (int u = 0; u < 4; ++u) {
                int ln = l0 + 8 + u;
                rnext[u] = (ln < LL) ? emb[(size_t)ln * (TT / 2)] : make_float2(0.f, 0.f);
                mnext[u] = (ln < LL) ? mk[ln] : 0;
            }
            float enA[4], enB[4];
            int mcn[4];
#pragma unroll
            for (int u = 0; u < 4; ++u) {
                enA[u] = __expf(rb[u].x);
                enB[u] = __expf(rb[u].y);
                mcn[u] = mraw[u];
            }

#pragma unroll
            for (int u = 0; u < 4; ++u) {
                int l = l0 + u;
                if (l < LL) {
                    int buf = l & 1;
                    ((float2*)sh[w][buf])[lane] = make_float2(sa, sb);
                    __syncwarp();
                    if (u & 1) {   // normalize every 2nd step
                        float qA, qB, r;
                        matvec2r(sh[w][buf], colA, colB, qA, qB, r);
                        float inv = __fdividef(1.f, r);
                        if (mcur[u]) {
                            sa = qA * inv * ebA[u];
                            sb = qB * inv * ebB[u];
                        }
                    } else {       // unscaled step (growth bounded, cancels)
                        float qA, qB;
                        matvec2(sh[w][buf], colA, colB, qA, qB);
                        if (mcur[u]) {
                            sa = qA * ebA[u];
                            sb = qB * ebB[u];
                        }
                    }
                    ((float2*)(sA + (size_t)l * BB * TT + b * TT))[lane] =
                        make_float2(sa, sb);
                }
            }
#pragma unroll
            for (int u = 0; u < 4; ++u) {
                ebA[u] = enA[u]; ebB[u] = enB[u]; mcur[u] = mcn[u];
                rb[u] = rnext[u]; mraw[u] = mnext[u];
            }
        }
    } else {
        // ================= BACKWARD =================
        const int b = task - BB;

        // E rows jA=tAi, jB=tBi packed over k
        unsigned long long rowA[TT / 2], rowB[TT / 2];
#pragma unroll
        for (int k2 = 0; k2 < TT / 2; ++k2) {
            rowA[k2] = pack2(expf(trans[tAi * TT + 2 * k2]),
                             expf(trans[tAi * TT + 2 * k2 + 1]));
            rowB[k2] = pack2(expf(trans[tBi * TT + 2 * k2]),
                             expf(trans[tBi * TT + 2 * k2 + 1]));
        }

        const float2* emb = (const float2*)(em + (size_t)b * LL * TT) + lane;
        const int* mk = mask + b * LL;

        float sa = __expf(endt[tAi]);
        float sb = __expf(endt[tBi]);
        ((float2*)(g_sB + (size_t)(LL - 1) * BB * TT + b * TT))[lane] =
            make_float2(sa, sb);

        float ebA[4], ebB[4];
        float2 rb[4];
        int mcur[4], mraw[4];
#pragma unroll
        for (int u = 0; u < 4; ++u) {
            int ln = (LL - 1) - u;
            float2 v = emb[(size_t)ln * (TT / 2)];
            ebA[u] = __expf(v.x);
            ebB[u] = __expf(v.y);
            mcur[u] = mk[ln];
        }
#pragma unroll
        for (int u = 0; u < 4; ++u) {
            int ln = (LL - 5) - u;
            rb[u]   = (ln >= 1) ? emb[(size_t)ln * (TT / 2)] : make_float2(0.f, 0.f);
            mraw[u] = (ln >= 1) ? mk[ln] : 0;
        }

        for (int l0 = LL - 1; l0 >= 1; l0 -= 4) {
            float2 rnext[4];
            int mnext[4];
#pragma unroll
            for (int u = 0; u < 4; ++u) {
                int ln = l0 - 8 - u;
                rnext[u] = (ln >= 1) ? emb[(size_t)ln * (TT / 2)] : make_float2(0.f, 0.f);
                mnext[u] = (ln >= 1) ? mk[ln] : 0;
            }
            float enA[4], enB[4];
            int mcn[4];
#pragma unroll
            for (int u = 0; u < 4; ++u) {
                enA[u] = __expf(rb[u].x);
                enB[u] = __expf(rb[u].y);
                mcn[u] = mraw[u];
            }

#pragma unroll
            for (int u = 0; u < 4; ++u) {
                int l = l0 - u;
                if (l >= 1) {
                    // t[k] = exp(em_l[k]) * b_l[k]
                    float ta = sa * ebA[u];
                    float tb = sb * ebB[u];
                    int buf = l & 1;
                    ((float2*)sh[w][buf])[lane] = make_float2(ta, tb);
                    __syncwarp();
                    if (u & 1) {   // normalize every 2nd step
                        float qA, qB, r;
                        matvec2r(sh[w][buf], rowA, rowB, qA, qB, r);
                        float inv = __fdividef(1.f, r);
                        if (mcur[u]) {
                            sa = qA * inv;
                            sb = qB * inv;
                        }
                    } else {
                        float qA, qB;
                        matvec2(sh[w][buf], rowA, rowB, qA, qB);
                        if (mcur[u]) {
                            sa = qA;
                            sb = qB;
                        }
                    }
                    ((float2*)(g_sB + (size_t)(l - 1) * BB * TT + b * TT))[lane] =
                        make_float2(sa, sb);
                }
            }
#pragma unroll
            for (int u = 0; u < 4; ++u) {
                ebA[u] = enA[u]; ebB[u] = enB[u]; mcur[u] = mcn[u];
                rb[u] = rnext[u]; mraw[u] = mnext[u];
            }
        }
    }
}

// ---------------------------------------------------------------------------
// Combine: out[p, k] = sA[p,k]*sB[p,k] / sum_k(sA[p,k]*sB[p,k]).
// One position per 16 lanes, float4 per thread, shfl-only reduction.
// ---------------------------------------------------------------------------
__global__ __launch_bounds__(256) void crf_combine(
    float* __restrict__ outA)   // (L*B, T): in = sA, out = marginals
{
    const int lane = threadIdx.x & 31;
    const int warp = threadIdx.x >> 5;
    const int half = lane >> 4;          // which position within the warp
    const int sub  = lane & 15;          // float4 index within position
    const size_t p = (size_t)blockIdx.x * 16 + warp * 2 + half;

    const size_t f4 = p * (TT / 4) + sub;
    float4 a = ((const float4*)outA)[f4];
    float4 b = ((const float4*)g_sB)[f4];
    float4 v = make_float4(a.x * b.x, a.y * b.y, a.z * b.z, a.w * b.w);
    float s = (v.x + v.y) + (v.z + v.w);
    s += __shfl_xor_sync(0xffffffffu, s, 8);
    s += __shfl_xor_sync(0xffffffffu, s, 4);
    s += __shfl_xor_sync(0xffffffffu, s, 2);
    s += __shfl_xor_sync(0xffffffffu, s, 1);
    float inv = 1.f / s;
    ((float4*)outA)[f4] =
        make_float4(v.x * inv, v.y * inv, v.z * inv, v.w * inv);
}

extern "C" void kernel_launch(void* const* d_in, const int* in_sizes, int n_in,
                              void* d_out, int out_size) {
    const float* em    = (const float*)d_in[0];  // emissions (B,L,T)
    const float* start = (const float*)d_in[1];  // start_transitions (T)
    const float* endt  = (const float*)d_in[2];  // end_transitions (T)
    const float* trans = (const float*)d_in[3];  // transitions (T,T)
    const int*   mask  = (const int*)d_in[4];    // mask (B,L)
    float* out = (float*)d_out;                  // (L,B,T)

    crf_scan<<<(2 * BB) / 4, 128>>>(em, start, endt, trans, mask, out);
    crf_combine<<<(LL * BB) / 16, 256>>>(out);
}